// round 12
// baseline (speedup 1.0000x reference)
#include <cuda_runtime.h>
#include <cuda_fp16.h>
#include <cstdint>
#include <cstddef>

#define L_SEQ 512
#define BATCH 128
#define DIM   128
#define HID   512
#define OUTD  5
#define N3H   1536
#define MROWS 65536  // L_SEQ*BATCH

// U column permutation: cols [0,HID) = u0 unchanged. Cols [HID,3H) interleaved:
//   orig col n = HID + gate*HID + h  (gate 0=u1,1=u2; h channel)
//   perm  col n' = HID + (h>>1)*4 + gate*2 + (h&1)
// so for half2-channel pair hp the 4 values [u1.x,u1.y,u2.x,u2.y] are contiguous (8B).

// ---------------- scratch (static device globals; no allocations) ----------------
__device__ __align__(256) __half g_xh[MROWS * DIM];
__device__ __align__(256) __half g_W0t[N3H * DIM];
__device__ __align__(256) __half g_W1t[N3H * HID];
__device__ __align__(256) __half g_U[MROWS * N3H];
__device__ __align__(256) __half g_h1[MROWS * HID];
__device__ __align__(256) float  g_h2last[BATCH * HID];

// ---------------- helpers ----------------
__device__ __forceinline__ uint32_t smem_cast(const void* p)
{
    return (uint32_t)__cvta_generic_to_shared(p);
}

#define CP_ASYNC16(dst, src) asm volatile("cp.async.cg.shared.global [%0], [%1], 16;\n" :: "r"(dst), "l"(src))
#define CP_ASYNC8(dst, src)  asm volatile("cp.async.ca.shared.global [%0], [%1], 8;\n"  :: "r"(dst), "l"(src))
#define CP_ASYNC4(dst, src)  asm volatile("cp.async.ca.shared.global [%0], [%1], 4;\n"  :: "r"(dst), "l"(src))
#define CP_COMMIT()          asm volatile("cp.async.commit_group;\n")
#define CP_WAIT1()           asm volatile("cp.async.wait_group 1;\n")
#define CP_WAIT14()          asm volatile("cp.async.wait_group 14;\n")

__device__ __forceinline__ float tanh_approx(float x)
{
    float t;
    asm("tanh.approx.f32 %0, %1;" : "=f"(t) : "f"(x));
    return t;
}

// ---------------- conversion kernels ----------------
__global__ void f2h_kernel(const float* __restrict__ s, __half* __restrict__ d, int n4)
{
    int i = blockIdx.x * blockDim.x + threadIdx.x;
    if (i < n4) {
        float4 v = reinterpret_cast<const float4*>(s)[i];
        __half2 lo = __floats2half2_rn(v.x, v.y);
        __half2 hi = __floats2half2_rn(v.z, v.w);
        uint2 pkt;
        pkt.x = *reinterpret_cast<uint32_t*>(&lo);
        pkt.y = *reinterpret_cast<uint32_t*>(&hi);
        reinterpret_cast<uint2*>(d)[i] = pkt;
    }
}

// transpose + f2h + column permutation: Wt[perm(n)][k] = (half) W[k][n]
__global__ void trans_f2h_kernel(const float* __restrict__ W, __half* __restrict__ Wt,
                                 int K, int N)
{
    __shared__ float tile[32][33];
    int tx = threadIdx.x;
    int ty = threadIdx.y;
    int nb = blockIdx.x * 32;
    int kb = blockIdx.y * 32;
#pragma unroll
    for (int j = 0; j < 32; j += 8)
        tile[ty + j][tx] = W[(size_t)(kb + ty + j) * N + (nb + tx)];
    __syncthreads();
#pragma unroll
    for (int j = 0; j < 32; j += 8) {
        int nn = nb + ty + j;
        int np;
        if (nn < HID) {
            np = nn;
        } else {
            int jj   = nn - HID;
            int gate = jj >> 9;       // /HID (HID=512)
            int h    = jj & 511;
            np = HID + ((h >> 1) << 2) + (gate << 1) + (h & 1);
        }
        Wt[(size_t)np * K + (kb + tx)] = __float2half(tile[tx][ty + j]);
    }
}

// ---------------- GEMM: 128x128 tile, 256 thr, 3-stage (PROVEN config) ----------------
#define LDSM4(R0, R1, R2, R3, ADDR) \
    asm volatile("ldmatrix.sync.aligned.m8n8.x4.shared.b16 {%0,%1,%2,%3}, [%4];" \
                 : "=r"(R0), "=r"(R1), "=r"(R2), "=r"(R3) : "r"(ADDR))

#define MMA16816(C0, C1, C2, C3, A0, A1, A2, A3, B0, B1)                              \
    asm volatile("mma.sync.aligned.m16n8k16.row.col.f32.f16.f16.f32 "                  \
                 "{%0,%1,%2,%3}, {%4,%5,%6,%7}, {%8,%9}, {%0,%1,%2,%3};"               \
                 : "+f"(C0), "+f"(C1), "+f"(C2), "+f"(C3)                              \
                 : "r"(A0), "r"(A1), "r"(A2), "r"(A3), "r"(B0), "r"(B1))

__device__ __forceinline__ int sw_gran(int row, int seg)
{
    return ((row >> 1) << 3) | ((((row & 1) << 2) | seg) ^ ((row >> 1) & 7));
}

__global__ void __launch_bounds__(256, 2) gemm_kernel(
    const __half* __restrict__ A,
    const __half* __restrict__ B,
    const float* __restrict__ braw,   // raw SRU bias vector [2H]
    __half* __restrict__ C,
    int K)
{
    __shared__ __align__(1024) __half As[3][128 * 32];
    __shared__ __align__(1024) __half Bs[3][128 * 32];

    const int tid  = threadIdx.x;
    const int lane = tid & 31;
    const int wid  = tid >> 5;
    const int wm   = wid & 3;
    const int wn   = wid >> 2;
    const int m0   = blockIdx.y * 128;
    const int n0   = blockIdx.x * 128;
    // gate columns (n0>=HID, permuted u1/u2): scale 0.5 + bias 0.5*b for tanh-sigmoid
    const bool gatecols = (n0 >= HID);
    const float s = gatecols ? 0.5f : 1.f;

    auto load_tile = [&](int buf, int k0) {
        uint32_t as = smem_cast(&As[buf][0]);
        uint32_t bs = smem_cast(&Bs[buf][0]);
#pragma unroll
        for (int i = 0; i < 2; i++) {
            int lin = tid + i * 256;
            int row = lin >> 2;
            int seg = lin & 3;
            int g   = sw_gran(row, seg);
            CP_ASYNC16(as + g * 16, A + (size_t)(m0 + row) * K + (k0 + seg * 8));
            CP_ASYNC16(bs + g * 16, B + (size_t)(n0 + row) * K + (k0 + seg * 8));
        }
    };

    float acc[2][8][4];
#pragma unroll
    for (int mi = 0; mi < 2; mi++)
#pragma unroll
        for (int ni = 0; ni < 8; ni++)
#pragma unroll
            for (int j = 0; j < 4; j++) acc[mi][ni][j] = 0.f;

    const int T = K >> 5;
    load_tile(0, 0);
    CP_COMMIT();
    load_tile(1, 32);
    CP_COMMIT();

    const int a_row_base = wm * 32 + (lane & 15);
    const int a_koff     = lane >> 4;
    const int b_row_base = wn * 64 + (lane & 7) + ((lane & 16) ? 8 : 0);
    const int b_koff     = (lane >> 3) & 1;

    for (int t = 0; t < T; t++) {
        CP_WAIT1();
        __syncthreads();

        if (t + 2 < T) load_tile((t + 2) % 3, (t + 2) << 5);
        CP_COMMIT();

        int cur = t % 3;
        uint32_t as = smem_cast(&As[cur][0]);
        uint32_t bs = smem_cast(&Bs[cur][0]);
#pragma unroll
        for (int kc = 0; kc < 2; kc++) {
            uint32_t a[2][4];
#pragma unroll
            for (int mi = 0; mi < 2; mi++) {
                int row = a_row_base + mi * 16;
                int seg = kc * 2 + a_koff;
                LDSM4(a[mi][0], a[mi][1], a[mi][2], a[mi][3], as + sw_gran(row, seg) * 16);
            }
            uint32_t bf[8][2];
#pragma unroll
            for (int nb = 0; nb < 4; nb++) {
                int row = b_row_base + nb * 16;
                int seg = kc * 2 + b_koff;
                LDSM4(bf[2 * nb][0], bf[2 * nb][1], bf[2 * nb + 1][0], bf[2 * nb + 1][1],
                      bs + sw_gran(row, seg) * 16);
            }
#pragma unroll
            for (int mi = 0; mi < 2; mi++)
#pragma unroll
                for (int ni = 0; ni < 8; ni++)
                    MMA16816(acc[mi][ni][0], acc[mi][ni][1], acc[mi][ni][2], acc[mi][ni][3],
                             a[mi][0], a[mi][1], a[mi][2], a[mi][3],
                             bf[ni][0], bf[ni][1]);
        }
        __syncthreads();
    }

#pragma unroll
    for (int mi = 0; mi < 2; mi++) {
        int m = m0 + wm * 32 + mi * 16 + (lane >> 2);
#pragma unroll
        for (int ni = 0; ni < 8; ni++) {
            int n = n0 + wn * 64 + ni * 8 + (lane & 3) * 2;
            float2 bb;
            if (gatecols) {
                // permuted col n (even): j=n-HID, gate=(j>>1)&1, pair base h=(j>>2)*2
                int j    = n - HID;
                int gate = (j >> 1) & 1;
                bb = *reinterpret_cast<const float2*>(braw + gate * HID + (j >> 2) * 2);
                bb.x *= 0.5f; bb.y *= 0.5f;
            } else {
                bb.x = 0.f; bb.y = 0.f;
            }
            __half2 lo = __floats2half2_rn(fmaf(acc[mi][ni][0], s, bb.x),
                                           fmaf(acc[mi][ni][1], s, bb.y));
            __half2 hi = __floats2half2_rn(fmaf(acc[mi][ni][2], s, bb.x),
                                           fmaf(acc[mi][ni][3], s, bb.y));
            *reinterpret_cast<__half2*>(C + (size_t)m * N3H + n)       = lo;
            *reinterpret_cast<__half2*>(C + (size_t)(m + 8) * N3H + n) = hi;
        }
    }
}

// ---------------- SRU recurrence: 2 cp.asyncs/step (4B u0 + 8B u1u2), tanh sigmoid ----------------
#define RSTAGES 16

__global__ void __launch_bounds__(32) sru_rec_kernel(
    const __half* __restrict__ U,    // permuted layout, u1/u2 pre-scaled+biased
    const float* __restrict__ v,
    __half* __restrict__ hout,       // [L*B][H] fp16 (store_all)
    float* __restrict__ hlast,       // [B][H] fp32 (!store_all)
    int store_all)
{
    __shared__ __align__(128) __half2 sU0[RSTAGES][32];   // 2 KB
    __shared__ __align__(128) uint2   sU12[RSTAGES][32];  // 4 KB

    const int tid = threadIdx.x;
    const int b   = blockIdx.x >> 3;
    const int sub = blockIdx.x & 7;
    const int hp  = sub * 32 + tid;
    const int h   = hp << 1;

    float2 vf = *reinterpret_cast<const float2*>(v + h);
    float2 vr = *reinterpret_cast<const float2*>(v + HID + h);
    vf.x *= 0.5f; vf.y *= 0.5f;
    vr.x *= 0.5f; vr.y *= 0.5f;

    const char* src0  = (const char*)(U + (size_t)b * N3H + h);
    const char* src12 = (const char*)(U + (size_t)b * N3H + HID) + hp * 8;
    const size_t step_bytes = (size_t)BATCH * N3H * 2;
    const uint32_t sm0  = smem_cast(&sU0[0][tid]);
    const uint32_t sm12 = smem_cast(&sU12[0][tid]);

    auto load_stage = [&](int l, int s) {
        size_t off = (size_t)l * step_bytes;
        CP_ASYNC4(sm0  + (uint32_t)(s * 128), src0  + off);
        CP_ASYNC8(sm12 + (uint32_t)(s * 256), src12 + off);
    };

#pragma unroll
    for (int s = 0; s < RSTAGES - 1; s++) {
        load_stage(s, s);
        CP_COMMIT();
    }

    __half2* Hp = reinterpret_cast<__half2*>(hout) + (size_t)b * (HID / 2) + hp;
    const size_t hstep = (size_t)BATCH * (HID / 2);

    float cx = 0.f, cy = 0.f, hx = 0.f, hy = 0.f;

    for (int l = 0; l < L_SEQ; l++) {
        CP_WAIT14();

        int s = l & (RSTAGES - 1);
        float2 u0 = __half22float2(sU0[s][tid]);
        uint2  w  = sU12[s][tid];
        float2 u1 = __half22float2(*reinterpret_cast<__half2*>(&w.x));
        float2 u2 = __half22float2(*reinterpret_cast<__half2*>(&w.y));

        int ln = l + RSTAGES - 1;
        if (ln < L_SEQ) load_stage(ln, ln & (RSTAGES - 1));
        CP_COMMIT();

        float tfx = tanh_approx(fmaf(vf.x, cx, u1.x));
        float tfy = tanh_approx(fmaf(vf.y, cy, u1.y));
        float trx = tanh_approx(fmaf(vr.x, cx, u2.x));
        float try_ = tanh_approx(fmaf(vr.y, cy, u2.y));

        float fx = fmaf(tfx, 0.5f, 0.5f);
        float fy = fmaf(tfy, 0.5f, 0.5f);
        float rx = fmaf(trx, 0.5f, 0.5f);
        float ry = fmaf(try_, 0.5f, 0.5f);

        cx = fmaf(fx, cx - u0.x, u0.x);
        cy = fmaf(fy, cy - u0.y, u0.y);
        hx = rx * cx;
        hy = ry * cy;

        if (store_all) Hp[(size_t)l * hstep] = __floats2half2_rn(hx, hy);
    }

    if (!store_all) {
        hlast[b * HID + h]     = hx;
        hlast[b * HID + h + 1] = hy;
    }
}

// ---------------- final FC ----------------
__global__ void fc_kernel(const float* __restrict__ hl, const float* __restrict__ w,
                          const float* __restrict__ bias, float* __restrict__ out)
{
    int o = blockIdx.x;
    int b = blockIdx.y;
    float p = 0.f;
    for (int h = threadIdx.x; h < HID; h += 128)
        p += hl[b * HID + h] * w[o * HID + h];
#pragma unroll
    for (int s = 16; s > 0; s >>= 1) p += __shfl_down_sync(0xffffffffu, p, s);
    __shared__ float red[4];
    if ((threadIdx.x & 31) == 0) red[threadIdx.x >> 5] = p;
    __syncthreads();
    if (threadIdx.x == 0)
        out[b * OUTD + o] = red[0] + red[1] + red[2] + red[3] + bias[o];
}

// ---------------- launch ----------------
extern "C" void kernel_launch(void* const* d_in, const int* in_sizes, int n_in,
                              void* d_out, int out_size)
{
    const float* x   = (const float*)d_in[0];
    const float* W0  = (const float*)d_in[1];
    const float* v0  = (const float*)d_in[2];
    const float* b0  = (const float*)d_in[3];
    const float* W1  = (const float*)d_in[4];
    const float* v1  = (const float*)d_in[5];
    const float* b1  = (const float*)d_in[6];
    const float* fcw = (const float*)d_in[7];
    const float* fcb = (const float*)d_in[8];
    float* out = (float*)d_out;

    void *p_xh, *p_w0t, *p_w1t, *p_u, *p_h1, *p_h2l;
    cudaGetSymbolAddress(&p_xh,  g_xh);
    cudaGetSymbolAddress(&p_w0t, g_W0t);
    cudaGetSymbolAddress(&p_w1t, g_W1t);
    cudaGetSymbolAddress(&p_u,   g_U);
    cudaGetSymbolAddress(&p_h1,  g_h1);
    cudaGetSymbolAddress(&p_h2l, g_h2last);
    __half* xh  = (__half*)p_xh;
    __half* w0t = (__half*)p_w0t;
    __half* w1t = (__half*)p_w1t;
    __half* U   = (__half*)p_u;
    __half* h1  = (__half*)p_h1;
    float*  h2l = (float*)p_h2l;

    const int nx4 = MROWS * DIM / 4;
    f2h_kernel<<<(nx4 + 255) / 256, 256>>>(x, xh, nx4);                               // 0
    trans_f2h_kernel<<<dim3(N3H / 32, DIM / 32), dim3(32, 8)>>>(W0, w0t, DIM, N3H);   // 1

    // layer 0
    gemm_kernel<<<dim3(N3H / 128, MROWS / 128), 256>>>(xh, w0t, b0, U, DIM);          // 2
    sru_rec_kernel<<<BATCH * 8, 32>>>(U, v0, h1, h2l, 1);                             // 3 <- profiled
    trans_f2h_kernel<<<dim3(N3H / 32, HID / 32), dim3(32, 8)>>>(W1, w1t, HID, N3H);   // 4

    // layer 1
    gemm_kernel<<<dim3(N3H / 128, MROWS / 128), 256>>>(h1, w1t, b1, U, HID);          // 5
    sru_rec_kernel<<<BATCH * 8, 32>>>(U, v1, h1, h2l, 0);                             // 6

    // head
    fc_kernel<<<dim3(OUTD, BATCH), 128>>>(h2l, fcw, fcb, out);                        // 7
}